// round 4
// baseline (speedup 1.0000x reference)
#include <cuda_runtime.h>
#include <stdint.h>

// ---------------------------------------------------------------------------
// extract_high_freq via db4 wavelet, images: [96][512][512] fp32
//   lo_w, hi_w = row-DWT(data)                   (m = 259 per row)
//   lo_rec     = lo_w + Bcol(col-detail(lo_w))   (rank-1 correction)
//   hi_rec     = 2 * hi_w                        (perfect reconstruction)
//   out        = row-IDWT(lo_rec, hi_rec)
// K1 produces lo_w / hi_w; K2 (fused) does column fix + row IDWT -> out.
// ---------------------------------------------------------------------------

#define N     512
#define M     259          // (512+7)/2
#define MP    288          // padded stride (1152 B, 128B-aligned rows)
#define NIMG  96
#define NROWS (NIMG * N)
#define KW    35           // lo-k columns per fused tile (32 outputs + 3 halo)
#define KWP   36           // padded smem stride

#define DL0 (-0.010597401784997278f)
#define DL1 ( 0.032883011666982945f)
#define DL2 ( 0.030841381835986965f)
#define DL3 (-0.18703481171888114f)
#define DL4 (-0.02798376941698385f)
#define DL5 ( 0.6308807679295904f)
#define DL6 ( 0.7148465705525415f)
#define DL7 ( 0.23037781330885523f)

// REC_LO[j] = DEC_LO[7-j] ; REC_HI[j] = (-1)^j * DEC_LO[j]
#define REC_LO_INIT  { DL7,  DL6,  DL5,  DL4,  DL3,  DL2,  DL1,  DL0 }
#define REC_HI_INIT  { DL0, -DL1,  DL2, -DL3,  DL4, -DL5,  DL6, -DL7 }
#define REC_HI2_INIT { 2*DL0, -2*DL1, 2*DL2, -2*DL3, 2*DL4, -2*DL5, 2*DL6, -2*DL7 }

__device__ float g_lo[(size_t)NIMG * N * MP];
__device__ float g_hi[(size_t)NIMG * N * MP];

__device__ __forceinline__ int mirN(int i) {
    if (i < 0)  i = -1 - i;
    if (i >= N) i = 2 * N - 1 - i;
    return i;
}

// ---------------------------------------------------------------------------
// K1: row DWT, no smem. 8 rows/block, 64 threads/row.
// Thread j computes k = 4j..4j+3 from window x[8j-6 .. 8j+7] (14 floats,
// LDG.64 + 3x LDG.128, no waste), stores 2x STG.128.
// ---------------------------------------------------------------------------
__global__ void __launch_bounds__(512) k_row_dwt(const float* __restrict__ x)
{
    const int j   = threadIdx.x;                      // 0..63
    const int row = blockIdx.x * 8 + threadIdx.y;

    const float* xr = x + (size_t)row * N;
    float* lo = g_lo + (size_t)row * MP;
    float* hi = g_hi + (size_t)row * MP;

    const float rl[8] = REC_LO_INIT;
    const float rh[8] = REC_HI_INIT;

    if (j >= 1) {
        // interior: window x[8j-6 .. 8j+7], fully inside [2, 511]
        const float2 w0 = *(const float2*)(xr + 8 * j - 6);
        const float4 w1 = *(const float4*)(xr + 8 * j - 4);
        const float4 w2 = *(const float4*)(xr + 8 * j);
        const float4 w3 = *(const float4*)(xr + 8 * j + 4);
        const float win[14] = { w0.x, w0.y,
                                w1.x, w1.y, w1.z, w1.w,
                                w2.x, w2.y, w2.z, w2.w,
                                w3.x, w3.y, w3.z, w3.w };
        float a[4], d[4];
#pragma unroll
        for (int q = 0; q < 4; ++q) {
            float aa = 0.f, dd = 0.f;
#pragma unroll
            for (int i = 0; i < 8; ++i) {
                aa = fmaf(win[2 * q + i], rl[i], aa);
                dd = fmaf(win[2 * q + i], rh[i], dd);
            }
            a[q] = aa; d[q] = dd;
        }
        *(float4*)(lo + 4 * j) = make_float4(a[0], a[1], a[2], a[3]);
        *(float4*)(hi + 4 * j) = make_float4(d[0], d[1], d[2], d[3]);
    } else {
        // j == 0: k = 0..3 with mirrored extension
        float a[4], d[4];
#pragma unroll
        for (int q = 0; q < 4; ++q) {
            const int e0 = 2 * q - 6;
            float aa = 0.f, dd = 0.f;
#pragma unroll
            for (int i = 0; i < 8; ++i) {
                const float v = xr[mirN(e0 + i)];
                aa = fmaf(v, rl[i], aa);
                dd = fmaf(v, rh[i], dd);
            }
            a[q] = aa; d[q] = dd;
        }
        *(float4*)(lo) = make_float4(a[0], a[1], a[2], a[3]);
        *(float4*)(hi) = make_float4(d[0], d[1], d[2], d[3]);
    }

    // tail k = 256..258 on threads j = 1..3 (right mirrored)
    if (j >= 1 && j <= 3) {
        const int kk = 255 + j;
        const int e0 = 2 * kk - 6;
        float aa = 0.f, dd = 0.f;
#pragma unroll
        for (int i = 0; i < 8; ++i) {
            const float v = xr[mirN(e0 + i)];
            aa = fmaf(v, rl[i], aa);
            dd = fmaf(v, rh[i], dd);
        }
        lo[kk] = aa;
        hi[kk] = dd;
    }
}

// ---------------------------------------------------------------------------
// K2 (fused): per (image, k-tile) block.
//   tile covers lo-k columns [32*tile, 32*tile+35) and out cols [64*tile, +64)
//   phase 0: load xs[r][kk] = lo_w[r][k0+kk]              (512 x 35)
//   phase 1: ds[kr][kk] = column detail of xs along r     (259 x 35)
//   phase 2: xs[t][kk] += Bcol(ds) (in-place lo_rec)
//   phase 3: out[r][2(k0+x)+{0,1}] = row-IDWT(xs window, 2*hi_w window)
// ---------------------------------------------------------------------------
__global__ void __launch_bounds__(512) k_col_row(float* __restrict__ out)
{
    extern __shared__ float sm[];
    float* xs = sm;               // [N][KWP]
    float* ds = sm + N * KWP;     // [M][KWP]

    const int x    = threadIdx.x;             // 0..31
    const int ty   = threadIdx.y;             // 0..15
    const int tile = blockIdx.x;              // 0..7
    const int img  = blockIdx.y;              // 0..95
    const int k0   = tile * 32;

    const float* lo_img = g_lo + (size_t)img * N * MP;

    // phase 0: load lo tile (all indices k0+kk <= 258, no bounds checks)
#pragma unroll 4
    for (int r = ty; r < N; r += 16) {
        const float* lr = lo_img + (size_t)r * MP + k0;
        xs[r * KWP + x] = lr[x];
        if (x < 3) xs[r * KWP + 32 + x] = lr[32 + x];
    }
    __syncthreads();

    const float rh[8] = REC_HI_INIT;

    // phase 1: column detail along r for each of the 35 columns
    for (int cc = x; cc < KW; cc += 32) {
        for (int kr = ty; kr < M; kr += 16) {
            const int e0 = 2 * kr - 6;
            float d;
            if (kr >= 3 && kr <= 255) {
                const float* p = xs + e0 * KWP + cc;
                d =      p[0 * KWP] * rh[0];
                d = fmaf(p[1 * KWP], rh[1], d);
                d = fmaf(p[2 * KWP], rh[2], d);
                d = fmaf(p[3 * KWP], rh[3], d);
                d = fmaf(p[4 * KWP], rh[4], d);
                d = fmaf(p[5 * KWP], rh[5], d);
                d = fmaf(p[6 * KWP], rh[6], d);
                d = fmaf(p[7 * KWP], rh[7], d);
            } else {
                d = 0.f;
#pragma unroll
                for (int i = 0; i < 8; ++i)
                    d = fmaf(xs[mirN(e0 + i) * KWP + cc], rh[i], d);
            }
            ds[kr * KWP + cc] = d;
        }
    }
    __syncthreads();

    // phase 2: in-place correction xs[t] += Bcol(ds). parity(t) == parity(ty).
    for (int cc = x; cc < KW; cc += 32) {
        if (ty & 1) {
            for (int t = ty; t < N; t += 16) {
                const int k0c = (t - 1) >> 1;
                const float* p = ds + k0c * KWP + cc;
                float b;
                b =      p[0 * KWP] * rh[7];
                b = fmaf(p[1 * KWP], rh[5], b);
                b = fmaf(p[2 * KWP], rh[3], b);
                b = fmaf(p[3 * KWP], rh[1], b);
                xs[t * KWP + cc] += b;
            }
        } else {
            for (int t = ty; t < N; t += 16) {
                const int k0c = t >> 1;
                const float* p = ds + k0c * KWP + cc;
                float b;
                b =      p[0 * KWP] * rh[6];
                b = fmaf(p[1 * KWP], rh[4], b);
                b = fmaf(p[2 * KWP], rh[2], b);
                b = fmaf(p[3 * KWP], rh[0], b);
                xs[t * KWP + cc] += b;
            }
        }
    }
    __syncthreads();

    // phase 3: row IDWT. u = k0 + x; out t = 2u, 2u+1. hi_w read from global.
    const float rl[8]  = REC_LO_INIT;
    const float rh2[8] = REC_HI2_INIT;
    const float* hi_img = g_hi + (size_t)img * N * MP;
    float* out_img = out + (size_t)img * N * N;

#pragma unroll 2
    for (int r = ty; r < N; r += 16) {
        const float* hr = hi_img + (size_t)r * MP + k0 + x;
        const float d0 = hr[0], d1 = hr[1], d2 = hr[2], d3 = hr[3];
        const float* ar = xs + r * KWP + x;
        const float a0 = ar[0], a1 = ar[1], a2 = ar[2], a3 = ar[3];

        float ev, od;
        ev =      a0 * rl[6];
        ev = fmaf(a1,  rl[4], ev);
        ev = fmaf(a2,  rl[2], ev);
        ev = fmaf(a3,  rl[0], ev);
        ev = fmaf(d0,  rh2[6], ev);
        ev = fmaf(d1,  rh2[4], ev);
        ev = fmaf(d2,  rh2[2], ev);
        ev = fmaf(d3,  rh2[0], ev);

        od =      a0 * rl[7];
        od = fmaf(a1,  rl[5], od);
        od = fmaf(a2,  rl[3], od);
        od = fmaf(a3,  rl[1], od);
        od = fmaf(d0,  rh2[7], od);
        od = fmaf(d1,  rh2[5], od);
        od = fmaf(d2,  rh2[3], od);
        od = fmaf(d3,  rh2[1], od);

        *(float2*)(out_img + (size_t)r * N + 2 * (k0 + x)) = make_float2(ev, od);
    }
}

// ---------------------------------------------------------------------------
extern "C" void kernel_launch(void* const* d_in, const int* in_sizes, int n_in,
                              void* d_out, int out_size)
{
    const float* data = (const float*)d_in[0];
    float* out = (float*)d_out;
    (void)in_sizes; (void)n_in; (void)out_size;

    const int k2_smem = (N * KWP + M * KWP) * (int)sizeof(float);  // 111024 B
    cudaFuncSetAttribute(k_col_row, cudaFuncAttributeMaxDynamicSharedMemorySize,
                         k2_smem);

    k_row_dwt<<<NROWS / 8, dim3(64, 8)>>>(data);
    k_col_row<<<dim3(8, NIMG), dim3(32, 16), k2_smem>>>(out);
}

// round 5
// speedup vs baseline: 1.3287x; 1.3287x over previous
#include <cuda_runtime.h>
#include <stdint.h>

// ---------------------------------------------------------------------------
// extract_high_freq via db4 wavelet, images: [96][512][512] fp32
//   lo_w, hi_w = row-DWT(data)                   (m = 259 per row)
//   lo_rec     = lo_w + Bcol(col-detail(lo_w))   (row-LOCAL correction, +/-7)
//   hi_rec     = 2 * hi_w
//   out        = row-IDWT(lo_rec, hi_rec)
// K1: row DWT -> g_lo, g_hi.   K2: row-band fused correction + row IDWT.
// ---------------------------------------------------------------------------

#define N     512
#define M     259          // (512+7)/2
#define MP    288          // padded stride (1152 B, 128B-aligned rows)
#define NIMG  96
#define NROWS (NIMG * N)

#define TR    32           // output rows per fused block
#define LR    (TR + 12)    // lo rows needed: [R0-6, R0+TR+5]  -> 44
#define QR    (TR / 2 + 3) // ds rows needed per block         -> 19
#define KS    260          // smem row stride (floats)

#define DL0 (-0.010597401784997278f)
#define DL1 ( 0.032883011666982945f)
#define DL2 ( 0.030841381835986965f)
#define DL3 (-0.18703481171888114f)
#define DL4 (-0.02798376941698385f)
#define DL5 ( 0.6308807679295904f)
#define DL6 ( 0.7148465705525415f)
#define DL7 ( 0.23037781330885523f)

// REC_LO[j] = DEC_LO[7-j] ; REC_HI[j] = (-1)^j * DEC_LO[j]
#define REC_LO_INIT  { DL7,  DL6,  DL5,  DL4,  DL3,  DL2,  DL1,  DL0 }
#define REC_HI_INIT  { DL0, -DL1,  DL2, -DL3,  DL4, -DL5,  DL6, -DL7 }
#define REC_HI2_INIT { 2*DL0, -2*DL1, 2*DL2, -2*DL3, 2*DL4, -2*DL5, 2*DL6, -2*DL7 }

__device__ float g_lo[(size_t)NIMG * N * MP];
__device__ float g_hi[(size_t)NIMG * N * MP];

__device__ __forceinline__ int mirN(int i) {
    if (i < 0)  i = -1 - i;
    if (i >= N) i = 2 * N - 1 - i;
    return i;
}

// ---------------------------------------------------------------------------
// K1: row DWT, no smem. 8 rows/block, 64 threads/row.
// Thread j computes k = 4j..4j+3 from window x[8j-6 .. 8j+7].
// ---------------------------------------------------------------------------
__global__ void __launch_bounds__(512) k_row_dwt(const float* __restrict__ x)
{
    const int j   = threadIdx.x;                      // 0..63
    const int row = blockIdx.x * 8 + threadIdx.y;

    const float* xr = x + (size_t)row * N;
    float* lo = g_lo + (size_t)row * MP;
    float* hi = g_hi + (size_t)row * MP;

    const float rl[8] = REC_LO_INIT;
    const float rh[8] = REC_HI_INIT;

    if (j >= 1) {
        const float2 w0 = *(const float2*)(xr + 8 * j - 6);
        const float4 w1 = *(const float4*)(xr + 8 * j - 4);
        const float4 w2 = *(const float4*)(xr + 8 * j);
        const float4 w3 = *(const float4*)(xr + 8 * j + 4);
        const float win[14] = { w0.x, w0.y,
                                w1.x, w1.y, w1.z, w1.w,
                                w2.x, w2.y, w2.z, w2.w,
                                w3.x, w3.y, w3.z, w3.w };
        float a[4], d[4];
#pragma unroll
        for (int q = 0; q < 4; ++q) {
            float aa = 0.f, dd = 0.f;
#pragma unroll
            for (int i = 0; i < 8; ++i) {
                aa = fmaf(win[2 * q + i], rl[i], aa);
                dd = fmaf(win[2 * q + i], rh[i], dd);
            }
            a[q] = aa; d[q] = dd;
        }
        *(float4*)(lo + 4 * j) = make_float4(a[0], a[1], a[2], a[3]);
        *(float4*)(hi + 4 * j) = make_float4(d[0], d[1], d[2], d[3]);
    } else {
        float a[4], d[4];
#pragma unroll
        for (int q = 0; q < 4; ++q) {
            const int e0 = 2 * q - 6;
            float aa = 0.f, dd = 0.f;
#pragma unroll
            for (int i = 0; i < 8; ++i) {
                const float v = xr[mirN(e0 + i)];
                aa = fmaf(v, rl[i], aa);
                dd = fmaf(v, rh[i], dd);
            }
            a[q] = aa; d[q] = dd;
        }
        *(float4*)(lo) = make_float4(a[0], a[1], a[2], a[3]);
        *(float4*)(hi) = make_float4(d[0], d[1], d[2], d[3]);
    }

    if (j >= 1 && j <= 3) {                           // tail k = 256..258
        const int kk = 255 + j;
        const int e0 = 2 * kk - 6;
        float aa = 0.f, dd = 0.f;
#pragma unroll
        for (int i = 0; i < 8; ++i) {
            const float v = xr[mirN(e0 + i)];
            aa = fmaf(v, rl[i], aa);
            dd = fmaf(v, rh[i], dd);
        }
        lo[kk] = aa;
        hi[kk] = dd;
    }
}

// ---------------------------------------------------------------------------
// K2 (fused, row-band): block = (img, band). Output rows [R0, R0+TR).
//  P0: lo_s[i][k] = g_lo[img][mir(R0-6+i)][k]       i=0..LR-1  (full rows)
//  P1: ds[q][k]   = sum_j lo_s[2q+j][k] * rh[j]      q=0..QR-1
//  P2: lo_s[tt+6][k] += 4-tap(ds[q0..q0+3][k])       tt=0..TR-1 (in place)
//  P3: out[R0+tt][2u+{0,1}] = row-IDWT(lo_s[tt+6][u..u+3], 2*g_hi[...])
// blockDim (128,4), 66.6 KB smem, 3 CTA/SM.
// ---------------------------------------------------------------------------
__global__ void __launch_bounds__(512) k_fused(float* __restrict__ out)
{
    extern __shared__ float sm[];
    float* lo_s = sm;               // [LR][KS]
    float* ds   = sm + LR * KS;     // [QR][KS]

    const int tx  = threadIdx.x;    // 0..127
    const int ty  = threadIdx.y;    // 0..3
    const int img = blockIdx.y;
    const int R0  = blockIdx.x * TR;

    const float* lo_img = g_lo + (size_t)img * N * MP;
    const float* hi_img = g_hi + (size_t)img * N * MP;

    // P0: load LR full lo rows (mirrored at image edges)
#pragma unroll
    for (int i = ty; i < LR; i += 4) {
        const int gr = mirN(R0 - 6 + i);
        const float* src = lo_img + (size_t)gr * MP;
        float* dst = lo_s + i * KS;
        dst[tx]       = src[tx];
        dst[tx + 128] = src[tx + 128];
        if (tx < 3) dst[tx + 256] = src[tx + 256];
    }
    __syncthreads();

    const float rh[8] = REC_HI_INIT;

    // P1: column detail rows. ds[q][k], local lo rows 2q..2q+7.
#pragma unroll
    for (int q = ty; q < QR; q += 4) {
        const float* p0 = lo_s + 2 * q * KS;
#pragma unroll 2
        for (int ko = 0; ko < 2; ++ko) {
            const int k = tx + ko * 128;
            const float* p = p0 + k;
            float d;
            d =      p[0 * KS] * rh[0];
            d = fmaf(p[1 * KS], rh[1], d);
            d = fmaf(p[2 * KS], rh[2], d);
            d = fmaf(p[3 * KS], rh[3], d);
            d = fmaf(p[4 * KS], rh[4], d);
            d = fmaf(p[5 * KS], rh[5], d);
            d = fmaf(p[6 * KS], rh[6], d);
            d = fmaf(p[7 * KS], rh[7], d);
            ds[q * KS + k] = d;
        }
        if (tx < 3) {
            const int k = tx + 256;
            const float* p = p0 + k;
            float d;
            d =      p[0 * KS] * rh[0];
            d = fmaf(p[1 * KS], rh[1], d);
            d = fmaf(p[2 * KS], rh[2], d);
            d = fmaf(p[3 * KS], rh[3], d);
            d = fmaf(p[4 * KS], rh[4], d);
            d = fmaf(p[5 * KS], rh[5], d);
            d = fmaf(p[6 * KS], rh[6], d);
            d = fmaf(p[7 * KS], rh[7], d);
            ds[q * KS + k] = d;
        }
    }
    __syncthreads();

    // P2: in-place correction of lo_s rows 6..6+TR-1.
    // tt parity == ty parity (step 4).
#pragma unroll
    for (int tt = ty; tt < TR; tt += 4) {
        const int q0 = (tt & 1) ? (tt - 1) >> 1 : tt >> 1;
        const float* p0 = ds + q0 * KS;
        float* dst = lo_s + (tt + 6) * KS;
        const float c0 = (tt & 1) ? rh[7] : rh[6];
        const float c1 = (tt & 1) ? rh[5] : rh[4];
        const float c2 = (tt & 1) ? rh[3] : rh[2];
        const float c3 = (tt & 1) ? rh[1] : rh[0];
#pragma unroll 2
        for (int ko = 0; ko < 2; ++ko) {
            const int k = tx + ko * 128;
            const float* p = p0 + k;
            float b;
            b =      p[0 * KS] * c0;
            b = fmaf(p[1 * KS], c1, b);
            b = fmaf(p[2 * KS], c2, b);
            b = fmaf(p[3 * KS], c3, b);
            dst[k] += b;
        }
        if (tx < 3) {
            const int k = tx + 256;
            const float* p = p0 + k;
            float b;
            b =      p[0 * KS] * c0;
            b = fmaf(p[1 * KS], c1, b);
            b = fmaf(p[2 * KS], c2, b);
            b = fmaf(p[3 * KS], c3, b);
            dst[k] += b;
        }
    }
    __syncthreads();

    // P3: row IDWT to out. u = tx, tx+128; out cols 2u, 2u+1.
    const float rl[8]  = REC_LO_INIT;
    const float rh2[8] = REC_HI2_INIT;
    float* out_img = out + (size_t)img * N * N;

#pragma unroll
    for (int tt = ty; tt < TR; tt += 4) {
        const int t = R0 + tt;
        const float* ar_row = lo_s + (tt + 6) * KS;
        const float* hr_row = hi_img + (size_t)t * MP;
        float* o_row = out_img + (size_t)t * N;
#pragma unroll 2
        for (int uo = 0; uo < 2; ++uo) {
            const int u = tx + uo * 128;
            const float* ar = ar_row + u;
            const float* hr = hr_row + u;
            const float a0 = ar[0], a1 = ar[1], a2 = ar[2], a3 = ar[3];
            const float d0 = hr[0], d1 = hr[1], d2 = hr[2], d3 = hr[3];

            float ev, od;
            ev =      a0 * rl[6];
            ev = fmaf(a1,  rl[4], ev);
            ev = fmaf(a2,  rl[2], ev);
            ev = fmaf(a3,  rl[0], ev);
            ev = fmaf(d0,  rh2[6], ev);
            ev = fmaf(d1,  rh2[4], ev);
            ev = fmaf(d2,  rh2[2], ev);
            ev = fmaf(d3,  rh2[0], ev);

            od =      a0 * rl[7];
            od = fmaf(a1,  rl[5], od);
            od = fmaf(a2,  rl[3], od);
            od = fmaf(a3,  rl[1], od);
            od = fmaf(d0,  rh2[7], od);
            od = fmaf(d1,  rh2[5], od);
            od = fmaf(d2,  rh2[3], od);
            od = fmaf(d3,  rh2[1], od);

            *(float2*)(o_row + 2 * u) = make_float2(ev, od);
        }
    }
}

// ---------------------------------------------------------------------------
extern "C" void kernel_launch(void* const* d_in, const int* in_sizes, int n_in,
                              void* d_out, int out_size)
{
    const float* data = (const float*)d_in[0];
    float* out = (float*)d_out;
    (void)in_sizes; (void)n_in; (void)out_size;

    const int smem = (LR + QR) * KS * (int)sizeof(float);  // 65520 B
    cudaFuncSetAttribute(k_fused, cudaFuncAttributeMaxDynamicSharedMemorySize,
                         smem);

    k_row_dwt<<<NROWS / 8, dim3(64, 8)>>>(data);
    k_fused<<<dim3(N / TR, NIMG), dim3(128, 4), smem>>>(out);
}

// round 6
// speedup vs baseline: 1.7432x; 1.3120x over previous
#include <cuda_runtime.h>
#include <stdint.h>

// ---------------------------------------------------------------------------
// extract_high_freq via db4 wavelet, [96][512][512] fp32 — SINGLE fused kernel.
// Row-locality: out rows [R0, R0+TR) depend only on data rows [R0-6, R0+TR+5].
//   P0: lo_s[i] = row-DWT-approx(data[mir(R0-6+i)]), hi_s for own rows
//   P1: ds[qq]  = 8-tap column detail over lo_s rows 2qq..2qq+7
//   P2: lo_s[tt+6] += 4-tap(ds)          (in-place lo_rec)
//   P3: out[t] = row-IDWT(lo_s[tt+6], 2*hi_s[tt])
// ---------------------------------------------------------------------------

#define N     512
#define M     259          // (512+7)/2
#define NIMG  96

#define TR    16           // output rows per block
#define LOR   28           // lo rows: global [R0-6, R0+21]
#define QR    11           // ds rows: global q in [R0/2, R0/2+10]
#define KS    260          // smem row stride (floats), 1040 B (16B-aligned)

#define DL0 (-0.010597401784997278f)
#define DL1 ( 0.032883011666982945f)
#define DL2 ( 0.030841381835986965f)
#define DL3 (-0.18703481171888114f)
#define DL4 (-0.02798376941698385f)
#define DL5 ( 0.6308807679295904f)
#define DL6 ( 0.7148465705525415f)
#define DL7 ( 0.23037781330885523f)

// REC_LO[j] = DEC_LO[7-j] ; REC_HI[j] = (-1)^j * DEC_LO[j]
#define REC_LO_INIT  { DL7,  DL6,  DL5,  DL4,  DL3,  DL2,  DL1,  DL0 }
#define REC_HI_INIT  { DL0, -DL1,  DL2, -DL3,  DL4, -DL5,  DL6, -DL7 }
#define REC_HI2_INIT { 2*DL0, -2*DL1, 2*DL2, -2*DL3, 2*DL4, -2*DL5, 2*DL6, -2*DL7 }

__device__ __forceinline__ int mirN(int i) {
    if (i < 0)  i = -1 - i;
    if (i >= N) i = 2 * N - 1 - i;
    return i;
}

__global__ void __launch_bounds__(512) k_all(const float* __restrict__ x,
                                             float* __restrict__ out)
{
    extern __shared__ float sm[];
    float* lo_s = sm;                      // [LOR][KS]
    float* ds   = sm + LOR * KS;           // [QR][KS]
    float* hi_s = sm + (LOR + QR) * KS;    // [TR][KS]

    const int tx  = threadIdx.x;           // 0..127
    const int ty  = threadIdx.y;           // 0..3
    const int tid = ty * 128 + tx;
    const int img = blockIdx.y;
    const int R0  = blockIdx.x * TR;

    const float* ximg = x + (size_t)img * N * N;

    const float rl[8] = REC_LO_INIT;
    const float rh[8] = REC_HI_INIT;

    // ---------------- P0: row DWT of 28 data rows into smem ----------------
    // 8 row-groups of 64 threads; thread jj covers k = 4jj..4jj+3 from
    // data window x[8jj-6 .. 8jj+7] (LDG.64 + 3x LDG.128).
    {
        const int jj = tid & 63;
        const int rg = tid >> 6;
        for (int i = rg; i < LOR; i += 8) {
            const int gr = mirN(R0 - 6 + i);
            const float* xr = ximg + (size_t)gr * N;
            const bool own = (i >= 6) && (i < 6 + TR);
            float* lo = lo_s + i * KS;
            float* hi = hi_s + (i - 6) * KS;

            if (jj >= 1) {
                const float2 w0 = *(const float2*)(xr + 8 * jj - 6);
                const float4 w1 = *(const float4*)(xr + 8 * jj - 4);
                const float4 w2 = *(const float4*)(xr + 8 * jj);
                const float4 w3 = *(const float4*)(xr + 8 * jj + 4);
                const float win[14] = { w0.x, w0.y,
                                        w1.x, w1.y, w1.z, w1.w,
                                        w2.x, w2.y, w2.z, w2.w,
                                        w3.x, w3.y, w3.z, w3.w };
                float a[4], d[4];
#pragma unroll
                for (int q = 0; q < 4; ++q) {
                    float aa = 0.f, dd = 0.f;
#pragma unroll
                    for (int u = 0; u < 8; ++u) {
                        aa = fmaf(win[2 * q + u], rl[u], aa);
                        dd = fmaf(win[2 * q + u], rh[u], dd);
                    }
                    a[q] = aa; d[q] = dd;
                }
                *(float4*)(lo + 4 * jj) = make_float4(a[0], a[1], a[2], a[3]);
                if (own)
                    *(float4*)(hi + 4 * jj) = make_float4(d[0], d[1], d[2], d[3]);
            } else {
                float a[4], d[4];
#pragma unroll
                for (int q = 0; q < 4; ++q) {
                    const int e0 = 2 * q - 6;
                    float aa = 0.f, dd = 0.f;
#pragma unroll
                    for (int u = 0; u < 8; ++u) {
                        const float v = xr[mirN(e0 + u)];
                        aa = fmaf(v, rl[u], aa);
                        dd = fmaf(v, rh[u], dd);
                    }
                    a[q] = aa; d[q] = dd;
                }
                *(float4*)(lo) = make_float4(a[0], a[1], a[2], a[3]);
                if (own)
                    *(float4*)(hi) = make_float4(d[0], d[1], d[2], d[3]);
            }

            if (jj >= 1 && jj <= 3) {            // tail k = 256..258
                const int kk = 255 + jj;
                const int e0 = 2 * kk - 6;
                float aa = 0.f, dd = 0.f;
#pragma unroll
                for (int u = 0; u < 8; ++u) {
                    const float v = xr[mirN(e0 + u)];
                    aa = fmaf(v, rl[u], aa);
                    dd = fmaf(v, rh[u], dd);
                }
                lo[kk] = aa;
                if (own) hi[kk] = dd;
            }
        }
    }
    __syncthreads();

    // ---------------- P1: column detail rows ds[qq] -------------------------
    for (int qq = ty; qq < QR; qq += 4) {
        const float* p0 = lo_s + 2 * qq * KS;
        for (int k = tx; k < M; k += 128) {
            const float* p = p0 + k;
            float d;
            d =      p[0 * KS] * rh[0];
            d = fmaf(p[1 * KS], rh[1], d);
            d = fmaf(p[2 * KS], rh[2], d);
            d = fmaf(p[3 * KS], rh[3], d);
            d = fmaf(p[4 * KS], rh[4], d);
            d = fmaf(p[5 * KS], rh[5], d);
            d = fmaf(p[6 * KS], rh[6], d);
            d = fmaf(p[7 * KS], rh[7], d);
            ds[qq * KS + k] = d;
        }
    }
    __syncthreads();

    // ---------------- P2: in-place correction of own lo rows ---------------
    for (int tt = ty; tt < TR; tt += 4) {        // parity(tt) == parity(ty)
        const int q0 = (tt & 1) ? (tt - 1) >> 1 : tt >> 1;
        const float c0 = (tt & 1) ? rh[7] : rh[6];
        const float c1 = (tt & 1) ? rh[5] : rh[4];
        const float c2 = (tt & 1) ? rh[3] : rh[2];
        const float c3 = (tt & 1) ? rh[1] : rh[0];
        const float* p0 = ds + q0 * KS;
        float* dst = lo_s + (tt + 6) * KS;
        for (int k = tx; k < M; k += 128) {
            const float* p = p0 + k;
            float b;
            b =      p[0 * KS] * c0;
            b = fmaf(p[1 * KS], c1, b);
            b = fmaf(p[2 * KS], c2, b);
            b = fmaf(p[3 * KS], c3, b);
            dst[k] += b;
        }
    }
    __syncthreads();

    // ---------------- P3: row IDWT to out ----------------------------------
    const float rh2[8] = REC_HI2_INIT;
    float* out_img = out + (size_t)img * N * N;

    for (int tt = ty; tt < TR; tt += 4) {
        const int t = R0 + tt;
        const float* ar_row = lo_s + (tt + 6) * KS;
        const float* hr_row = hi_s + tt * KS;
        float* o_row = out_img + (size_t)t * N;
#pragma unroll 2
        for (int uo = 0; uo < 2; ++uo) {
            const int u = tx + uo * 128;
            const float a0 = ar_row[u],     a1 = ar_row[u + 1];
            const float a2 = ar_row[u + 2], a3 = ar_row[u + 3];
            const float d0 = hr_row[u],     d1 = hr_row[u + 1];
            const float d2 = hr_row[u + 2], d3 = hr_row[u + 3];

            float ev, od;
            ev =      a0 * rl[6];
            ev = fmaf(a1,  rl[4], ev);
            ev = fmaf(a2,  rl[2], ev);
            ev = fmaf(a3,  rl[0], ev);
            ev = fmaf(d0,  rh2[6], ev);
            ev = fmaf(d1,  rh2[4], ev);
            ev = fmaf(d2,  rh2[2], ev);
            ev = fmaf(d3,  rh2[0], ev);

            od =      a0 * rl[7];
            od = fmaf(a1,  rl[5], od);
            od = fmaf(a2,  rl[3], od);
            od = fmaf(a3,  rl[1], od);
            od = fmaf(d0,  rh2[7], od);
            od = fmaf(d1,  rh2[5], od);
            od = fmaf(d2,  rh2[3], od);
            od = fmaf(d3,  rh2[1], od);

            *(float2*)(o_row + 2 * u) = make_float2(ev, od);
        }
    }
}

// ---------------------------------------------------------------------------
extern "C" void kernel_launch(void* const* d_in, const int* in_sizes, int n_in,
                              void* d_out, int out_size)
{
    const float* data = (const float*)d_in[0];
    float* out = (float*)d_out;
    (void)in_sizes; (void)n_in; (void)out_size;

    const int smem = (LOR + QR + TR) * KS * (int)sizeof(float);  // 57200 B
    cudaFuncSetAttribute(k_all, cudaFuncAttributeMaxDynamicSharedMemorySize,
                         smem);

    k_all<<<dim3(N / TR, NIMG), dim3(128, 4), smem>>>(data, out);
}

// round 9
// speedup vs baseline: 1.9012x; 1.0906x over previous
#include <cuda_runtime.h>
#include <stdint.h>

// ---------------------------------------------------------------------------
// extract_high_freq via db4 wavelet, [96][512][512] fp32 — single fused kernel.
//   P0: lo_s[i] = row-DWT-approx(data[mir(R0-6+i)]); hi_s for own rows
//   P1: lr_s[tt] = 14-tap column conv of lo_s (fused detail+synthesis+identity)
//   P2: out[t]   = row-IDWT(lr_s[tt], 2*hi_s[tt])
// ---------------------------------------------------------------------------

#define N     512
#define M     259          // (512+7)/2
#define NIMG  96

#define TR    16           // output rows per block
#define LOR   28           // lo rows: global [R0-6, R0+21]
#define KS    260          // smem row stride (floats)

#define DL0 (-0.010597401784997278f)
#define DL1 ( 0.032883011666982945f)
#define DL2 ( 0.030841381835986965f)
#define DL3 (-0.18703481171888114f)
#define DL4 (-0.02798376941698385f)
#define DL5 ( 0.6308807679295904f)
#define DL6 ( 0.7148465705525415f)
#define DL7 ( 0.23037781330885523f)

// REC_LO[j] = DEC_LO[7-j] ; REC_HI[j] = (-1)^j * DEC_LO[j]
#define REC_LO_INIT  { DL7,  DL6,  DL5,  DL4,  DL3,  DL2,  DL1,  DL0 }
#define REC_HI_INIT  { DL0, -DL1,  DL2, -DL3,  DL4, -DL5,  DL6, -DL7 }
#define REC_HI2_INIT { 2*DL0, -2*DL1, 2*DL2, -2*DL3, 2*DL4, -2*DL5, 2*DL6, -2*DL7 }

// Combined column-correction weights (detail ∘ synthesis + identity).
// __host__ __device__ constexpr so device code can call; results constant-fold.
__host__ __device__ constexpr float rh_at(int j) {
    constexpr float rh[8] = REC_HI_INIT;
    return rh[j];
}
__host__ __device__ constexpr float we_at(int m) {  // even t: rows tt..tt+13
    float s = (m == 6) ? 1.0f : 0.0f;               // identity lo_w[t] at m=6
    for (int i = 0; i < 4; ++i) {
        const int j = m - 2 * i;
        if (j >= 0 && j < 8) s += rh_at(6 - 2 * i) * rh_at(j);
    }
    return s;
}
__host__ __device__ constexpr float wo_at(int m) {  // odd t: rows tt-1..tt+12
    float s = (m == 7) ? 1.0f : 0.0f;               // identity at m=7
    for (int i = 0; i < 4; ++i) {
        const int j = m - 2 * i;
        if (j >= 0 && j < 8) s += rh_at(7 - 2 * i) * rh_at(j);
    }
    return s;
}

__device__ __forceinline__ int mirN(int i) {
    if (i < 0)  i = -1 - i;
    if (i >= N) i = 2 * N - 1 - i;
    return i;
}

__global__ void __launch_bounds__(512) k_all(const float* __restrict__ x,
                                             float* __restrict__ out)
{
    extern __shared__ float sm[];
    float* lo_s = sm;                      // [LOR][KS]
    float* hi_s = sm + LOR * KS;           // [TR][KS]
    float* lr_s = sm + (LOR + TR) * KS;    // [TR][KS]

    const int tx  = threadIdx.x;           // 0..127
    const int ty  = threadIdx.y;           // 0..3
    const int tid = ty * 128 + tx;
    const int img = blockIdx.y;
    const int R0  = blockIdx.x * TR;

    const float* ximg = x + (size_t)img * N * N;

    const float rl[8] = REC_LO_INIT;
    const float rh[8] = REC_HI_INIT;

    // ---------------- P0: row DWT of 28 data rows into smem ----------------
    {
        const int jj = tid & 63;           // k = 4jj..4jj+3
        const int rg = tid >> 6;           // row group 0..7
        for (int i = rg; i < LOR; i += 8) {
            const int gr = mirN(R0 - 6 + i);
            const float* xr = ximg + (size_t)gr * N;
            const bool own = (i >= 6) && (i < 6 + TR);
            float* lo = lo_s + i * KS;
            float* hi = hi_s + (i - 6) * KS;

            if (jj >= 1) {
                const float2 w0 = *(const float2*)(xr + 8 * jj - 6);
                const float4 w1 = *(const float4*)(xr + 8 * jj - 4);
                const float4 w2 = *(const float4*)(xr + 8 * jj);
                const float4 w3 = *(const float4*)(xr + 8 * jj + 4);
                const float win[14] = { w0.x, w0.y,
                                        w1.x, w1.y, w1.z, w1.w,
                                        w2.x, w2.y, w2.z, w2.w,
                                        w3.x, w3.y, w3.z, w3.w };
                float a[4];
#pragma unroll
                for (int q = 0; q < 4; ++q) {
                    float aa = 0.f;
#pragma unroll
                    for (int u = 0; u < 8; ++u)
                        aa = fmaf(win[2 * q + u], rl[u], aa);
                    a[q] = aa;
                }
                *(float4*)(lo + 4 * jj) = make_float4(a[0], a[1], a[2], a[3]);
                if (own) {
                    float d[4];
#pragma unroll
                    for (int q = 0; q < 4; ++q) {
                        float dd = 0.f;
#pragma unroll
                        for (int u = 0; u < 8; ++u)
                            dd = fmaf(win[2 * q + u], rh[u], dd);
                        d[q] = dd;
                    }
                    *(float4*)(hi + 4 * jj) = make_float4(d[0], d[1], d[2], d[3]);
                }
            } else {
                float a[4], d[4];
#pragma unroll
                for (int q = 0; q < 4; ++q) {
                    const int e0 = 2 * q - 6;
                    float aa = 0.f, dd = 0.f;
#pragma unroll
                    for (int u = 0; u < 8; ++u) {
                        const float v = xr[mirN(e0 + u)];
                        aa = fmaf(v, rl[u], aa);
                        dd = fmaf(v, rh[u], dd);
                    }
                    a[q] = aa; d[q] = dd;
                }
                *(float4*)(lo) = make_float4(a[0], a[1], a[2], a[3]);
                if (own)
                    *(float4*)(hi) = make_float4(d[0], d[1], d[2], d[3]);
            }

            if (jj >= 1 && jj <= 3) {                // tail k = 256..258
                const int kk = 255 + jj;
                const int e0 = 2 * kk - 6;
                float aa = 0.f, dd = 0.f;
#pragma unroll
                for (int u = 0; u < 8; ++u) {
                    const float v = xr[mirN(e0 + u)];
                    aa = fmaf(v, rl[u], aa);
                    dd = fmaf(v, rh[u], dd);
                }
                lo[kk] = aa;
                if (own) hi[kk] = dd;
            }
        }
    }
    __syncthreads();

    // ------- P1: fused column correction, 14-tap, register window ----------
    // ty group handles output rows tt = 4ty..4ty+3 (windows share rows).
    {
        const float WE[14] = { we_at(0),  we_at(1),  we_at(2),  we_at(3),
                               we_at(4),  we_at(5),  we_at(6),  we_at(7),
                               we_at(8),  we_at(9),  we_at(10), we_at(11),
                               we_at(12), we_at(13) };
        const float WO[14] = { wo_at(0),  wo_at(1),  wo_at(2),  wo_at(3),
                               wo_at(4),  wo_at(5),  wo_at(6),  wo_at(7),
                               wo_at(8),  wo_at(9),  wo_at(10), wo_at(11),
                               wo_at(12), wo_at(13) };
        const int r0 = 4 * ty;
        for (int k = tx; k < M; k += 128) {
            float w[16];
#pragma unroll
            for (int i = 0; i < 16; ++i)
                w[i] = lo_s[(r0 + i) * KS + k];
            float e0 = 0.f, o0 = 0.f, e1 = 0.f, o1 = 0.f;
#pragma unroll
            for (int m = 0; m < 14; ++m) {
                e0 = fmaf(w[m],     WE[m], e0);
                o0 = fmaf(w[m],     WO[m], o0);
                e1 = fmaf(w[m + 2], WE[m], e1);
                o1 = fmaf(w[m + 2], WO[m], o1);
            }
            lr_s[(r0 + 0) * KS + k] = e0;
            lr_s[(r0 + 1) * KS + k] = o0;
            lr_s[(r0 + 2) * KS + k] = e1;
            lr_s[(r0 + 3) * KS + k] = o1;
        }
    }
    __syncthreads();

    // ---------------- P2: row IDWT to out (8 cols per thread) --------------
    {
        const float rh2[8] = REC_HI2_INIT;
        const int jj = tid & 63;            // cols 8jj..8jj+7, u0 = 4jj
        const int rg = tid >> 6;
        float* out_img = out + (size_t)img * N * N;

#pragma unroll 2
        for (int tt = rg; tt < TR; tt += 8) {
            const float* ar = lr_s + tt * KS + 4 * jj;
            const float* hr = hi_s + tt * KS + 4 * jj;
            const float4 a03 = *(const float4*)ar;
            const float2 a45 = *(const float2*)(ar + 4);
            const float  a6  = ar[6];
            const float4 d03 = *(const float4*)hr;
            const float2 d45 = *(const float2*)(hr + 4);
            const float  d6  = hr[6];
            const float a[7] = { a03.x, a03.y, a03.z, a03.w, a45.x, a45.y, a6 };
            const float d[7] = { d03.x, d03.y, d03.z, d03.w, d45.x, d45.y, d6 };

            float o[8];
#pragma unroll
            for (int p = 0; p < 4; ++p) {
                float ev, od;
                ev =      a[p]     * rl[6];
                ev = fmaf(a[p + 1],  rl[4], ev);
                ev = fmaf(a[p + 2],  rl[2], ev);
                ev = fmaf(a[p + 3],  rl[0], ev);
                ev = fmaf(d[p],      rh2[6], ev);
                ev = fmaf(d[p + 1],  rh2[4], ev);
                ev = fmaf(d[p + 2],  rh2[2], ev);
                ev = fmaf(d[p + 3],  rh2[0], ev);

                od =      a[p]     * rl[7];
                od = fmaf(a[p + 1],  rl[5], od);
                od = fmaf(a[p + 2],  rl[3], od);
                od = fmaf(a[p + 3],  rl[1], od);
                od = fmaf(d[p],      rh2[7], od);
                od = fmaf(d[p + 1],  rh2[5], od);
                od = fmaf(d[p + 2],  rh2[3], od);
                od = fmaf(d[p + 3],  rh2[1], od);

                o[2 * p]     = ev;
                o[2 * p + 1] = od;
            }

            float* orow = out_img + (size_t)(R0 + tt) * N + 8 * jj;
            *(float4*)(orow)     = make_float4(o[0], o[1], o[2], o[3]);
            *(float4*)(orow + 4) = make_float4(o[4], o[5], o[6], o[7]);
        }
    }
}

// ---------------------------------------------------------------------------
extern "C" void kernel_launch(void* const* d_in, const int* in_sizes, int n_in,
                              void* d_out, int out_size)
{
    const float* data = (const float*)d_in[0];
    float* out = (float*)d_out;
    (void)in_sizes; (void)n_in; (void)out_size;

    const int smem = (LOR + 2 * TR) * KS * (int)sizeof(float);  // 62400 B
    cudaFuncSetAttribute(k_all, cudaFuncAttributeMaxDynamicSharedMemorySize,
                         smem);

    k_all<<<dim3(N / TR, NIMG), dim3(128, 4), smem>>>(data, out);
}